// round 2
// baseline (speedup 1.0000x reference)
#include <cuda_runtime.h>

// fid[p] = clip( (va.vb)^2 / (|va|^2 |vb|^2), 0, 1 )
// va = tanh( relu(xa @ W1 + b1) @ W2 + b2 )   (quantum circuit is unitary -> cancels)

#define KDIM 784
#define KT   56
#define NKT  14   // 784 / 56

__global__ __launch_bounds__(256)
void qcm_fused(const float* __restrict__ img_a,
               const float* __restrict__ img_b,
               const float* __restrict__ W1,
               const float* __restrict__ b1,
               const float* __restrict__ W2,
               const float* __restrict__ b2,
               float* __restrict__ out)
{
    // GEMM tiles overlaid with the post-GEMM H tile (never live simultaneously)
    __shared__ union {
        struct { float As[64 * 57]; float Bs[56 * 64]; } g;  // 28928 B
        float Hs[64 * 65];                                    // 16640 B
    } sm;
    __shared__ float W2s[64 * 16];
    __shared__ float b1s[64];
    __shared__ float b2s[16];
    __shared__ float Vs[64 * 16];
    __shared__ float ssq[64];

    const int t  = threadIdx.x;
    const int tx = t & 15;       // 16 col-groups of 4
    const int ty = t >> 4;       // 16 row-groups of 4
    const int p0 = blockIdx.x * 32;   // 32 pairs per block

    // small params
    if (t < 64) b1s[t] = b1[t];
    if (t < 16) b2s[t] = b2[t];
    #pragma unroll
    for (int i = 0; i < 4; ++i) W2s[t + i * 256] = W2[t + i * 256];

    float acc[4][4];
    #pragma unroll
    for (int i = 0; i < 4; ++i)
        #pragma unroll
        for (int j = 0; j < 4; ++j) acc[i][j] = 0.0f;

    // ---- main GEMM: rows 0..31 = img_a pairs p0..p0+31, rows 32..63 = img_b ----
    for (int kt = 0; kt < NKT; ++kt) {
        const int k0 = kt * KT;

        // load A tile: 64 rows x 56 K, 896 float4
        #pragma unroll
        for (int i = 0; i < 4; ++i) {
            int idx4 = t + i * 256;
            if (idx4 < 896) {
                int r = idx4 / 14;
                int q = idx4 - r * 14;
                const float* src = (r < 32
                        ? img_a + (size_t)(p0 + r) * KDIM
                        : img_b + (size_t)(p0 + r - 32) * KDIM) + k0 + q * 4;
                float4 v = *(const float4*)src;
                float* dst = &sm.g.As[r * 57 + q * 4];
                dst[0] = v.x; dst[1] = v.y; dst[2] = v.z; dst[3] = v.w;
            }
        }
        // load B tile: 56 K x 64 N (W1 natural layout), 896 float4
        #pragma unroll
        for (int i = 0; i < 4; ++i) {
            int idx4 = t + i * 256;
            if (idx4 < 896) {
                int kk = idx4 >> 4;
                int nq = idx4 & 15;
                *(float4*)&sm.g.Bs[kk * 64 + nq * 4] =
                    *(const float4*)(W1 + (size_t)(k0 + kk) * 64 + nq * 4);
            }
        }
        __syncthreads();

        #pragma unroll 14
        for (int kk = 0; kk < KT; ++kk) {
            float a0 = sm.g.As[(ty * 4 + 0) * 57 + kk];
            float a1 = sm.g.As[(ty * 4 + 1) * 57 + kk];
            float a2 = sm.g.As[(ty * 4 + 2) * 57 + kk];
            float a3 = sm.g.As[(ty * 4 + 3) * 57 + kk];
            float4 bv = *(const float4*)&sm.g.Bs[kk * 64 + tx * 4];
            acc[0][0] += a0 * bv.x; acc[0][1] += a0 * bv.y;
            acc[0][2] += a0 * bv.z; acc[0][3] += a0 * bv.w;
            acc[1][0] += a1 * bv.x; acc[1][1] += a1 * bv.y;
            acc[1][2] += a1 * bv.z; acc[1][3] += a1 * bv.w;
            acc[2][0] += a2 * bv.x; acc[2][1] += a2 * bv.y;
            acc[2][2] += a2 * bv.z; acc[2][3] += a2 * bv.w;
            acc[3][0] += a3 * bv.x; acc[3][1] += a3 * bv.y;
            acc[3][2] += a3 * bv.z; acc[3][3] += a3 * bv.w;
        }
        __syncthreads();
    }

    // ---- H = relu(acc + b1) into smem (overlays GEMM tiles) ----
    #pragma unroll
    for (int i = 0; i < 4; ++i) {
        int r = ty * 4 + i;
        #pragma unroll
        for (int j = 0; j < 4; ++j) {
            int n = tx * 4 + j;
            sm.Hs[r * 65 + n] = fmaxf(acc[i][j] + b1s[n], 0.0f);
        }
    }
    __syncthreads();

    // ---- v = tanh(H @ W2 + b2); 4 threads per row, 4 outputs each ----
    {
        int row = t >> 2;
        int seg = t & 3;
        float4 bb = *(const float4*)&b2s[seg * 4];
        float s0 = bb.x, s1 = bb.y, s2 = bb.z, s3 = bb.w;
        #pragma unroll 16
        for (int kk = 0; kk < 64; ++kk) {
            float  h = sm.Hs[row * 65 + kk];
            float4 w = *(const float4*)&W2s[kk * 16 + seg * 4];
            s0 += h * w.x; s1 += h * w.y; s2 += h * w.z; s3 += h * w.w;
        }
        s0 = tanhf(s0); s1 = tanhf(s1); s2 = tanhf(s2); s3 = tanhf(s3);
        float sq = s0 * s0 + s1 * s1 + s2 * s2 + s3 * s3;
        sq += __shfl_xor_sync(0xffffffffu, sq, 1);
        sq += __shfl_xor_sync(0xffffffffu, sq, 2);
        *(float4*)&Vs[row * 16 + seg * 4] = make_float4(s0, s1, s2, s3);
        if (seg == 0) ssq[row] = sq;
    }
    __syncthreads();

    // ---- fid = (va.vb)^2 / (|va|^2 |vb|^2), clipped ----
    if (t < 128) {
        int p   = t >> 2;
        int seg = t & 3;
        float4 a = *(const float4*)&Vs[p * 16 + seg * 4];
        float4 b = *(const float4*)&Vs[(p + 32) * 16 + seg * 4];
        float d = a.x * b.x + a.y * b.y + a.z * b.z + a.w * b.w;
        d += __shfl_xor_sync(0xffffffffu, d, 1);
        d += __shfl_xor_sync(0xffffffffu, d, 2);
        if (seg == 0) {
            float fid = (d * d) / (ssq[p] * ssq[p + 32]);
            out[p0 + p] = fminf(fmaxf(fid, 0.0f), 1.0f);
        }
    }
}

extern "C" void kernel_launch(void* const* d_in, const int* in_sizes, int n_in,
                              void* d_out, int out_size)
{
    const float* img_a = (const float*)d_in[0];
    const float* img_b = (const float*)d_in[1];
    const float* W1    = (const float*)d_in[2];
    const float* b1    = (const float*)d_in[3];
    const float* W2    = (const float*)d_in[4];
    const float* b2    = (const float*)d_in[5];
    // d_in[6] = theta: unused — the circuit is unitary, fidelity is invariant.
    float* out = (float*)d_out;

    int pairs  = out_size;          // 65536
    int blocks = pairs / 32;        // 32 pairs per block
    qcm_fused<<<blocks, 256>>>(img_a, img_b, W1, b1, W2, b2, out);
}

// round 3
// speedup vs baseline: 1.0125x; 1.0125x over previous
#include <cuda_runtime.h>

// fid[p] = clip( (va.vb)^2 / (|va|^2 |vb|^2), 0, 1 )
// va = tanh( relu(xa @ W1 + b1) @ W2 + b2 )   (quantum circuit is unitary -> cancels)

#define KDIM 784
#define KT   56
#define NKT  14      // 784 / 56
#define ASTR 60      // padded A-tile row stride (floats), 16B-aligned, multiple of 4

__global__ __launch_bounds__(256)
void qcm_fused(const float* __restrict__ img_a,
               const float* __restrict__ img_b,
               const float* __restrict__ W1,
               const float* __restrict__ b1,
               const float* __restrict__ W2,
               const float* __restrict__ b2,
               float* __restrict__ out)
{
    // GEMM tiles overlaid with the post-GEMM H tile (never live simultaneously)
    __shared__ union {
        struct { float As[64 * ASTR]; float Bs[56 * 64]; } g;  // 29696 B
        float Hs[64 * 65];                                      // 16640 B
    } sm;
    __shared__ float W2s[64 * 16];
    __shared__ float b1s[64];
    __shared__ float b2s[16];
    __shared__ float Vs[64 * 16];
    __shared__ float ssq[64];

    const int t  = threadIdx.x;
    const int tx = t & 15;       // 16 col-groups of 4
    const int ty = t >> 4;       // 16 row-groups of 4
    const int p0 = blockIdx.x * 32;   // 32 pairs per block

    // small params
    if (t < 64) b1s[t] = b1[t];
    if (t < 16) b2s[t] = b2[t];
    #pragma unroll
    for (int i = 0; i < 4; ++i) W2s[t + i * 256] = W2[t + i * 256];

    float acc[4][4];
    #pragma unroll
    for (int i = 0; i < 4; ++i)
        #pragma unroll
        for (int j = 0; j < 4; ++j) acc[i][j] = 0.0f;

    // ---- main GEMM: rows 0..31 = img_a pairs p0..p0+31, rows 32..63 = img_b ----
    for (int kt = 0; kt < NKT; ++kt) {
        const int k0 = kt * KT;

        // load A tile: 64 rows x 56 K, 896 float4, padded stride ASTR
        #pragma unroll
        for (int i = 0; i < 4; ++i) {
            int idx4 = t + i * 256;
            if (idx4 < 896) {
                int r = idx4 / 14;
                int q = idx4 - r * 14;
                const float* src = (r < 32
                        ? img_a + (size_t)(p0 + r) * KDIM
                        : img_b + (size_t)(p0 + r - 32) * KDIM) + k0 + q * 4;
                *(float4*)&sm.g.As[r * ASTR + q * 4] = *(const float4*)src;
            }
        }
        // load B tile: 56 K x 64 N (W1 natural layout), 896 float4
        #pragma unroll
        for (int i = 0; i < 4; ++i) {
            int idx4 = t + i * 256;
            if (idx4 < 896) {
                int kk = idx4 >> 4;
                int nq = idx4 & 15;
                *(float4*)&sm.g.Bs[kk * 64 + nq * 4] =
                    *(const float4*)(W1 + (size_t)(k0 + kk) * 64 + nq * 4);
            }
        }
        __syncthreads();

        // 4 kk-steps per iteration; each A row fetched once as float4
        #pragma unroll
        for (int k4 = 0; k4 < KT; k4 += 4) {
            float4 A0 = *(const float4*)&sm.g.As[(ty * 4 + 0) * ASTR + k4];
            float4 A1 = *(const float4*)&sm.g.As[(ty * 4 + 1) * ASTR + k4];
            float4 A2 = *(const float4*)&sm.g.As[(ty * 4 + 2) * ASTR + k4];
            float4 A3 = *(const float4*)&sm.g.As[(ty * 4 + 3) * ASTR + k4];

#define QCM_STEP(U, C)                                                        \
            {                                                                 \
                float4 bv = *(const float4*)&sm.g.Bs[(k4 + U) * 64 + tx * 4]; \
                acc[0][0] += A0.C * bv.x; acc[0][1] += A0.C * bv.y;           \
                acc[0][2] += A0.C * bv.z; acc[0][3] += A0.C * bv.w;           \
                acc[1][0] += A1.C * bv.x; acc[1][1] += A1.C * bv.y;           \
                acc[1][2] += A1.C * bv.z; acc[1][3] += A1.C * bv.w;           \
                acc[2][0] += A2.C * bv.x; acc[2][1] += A2.C * bv.y;           \
                acc[2][2] += A2.C * bv.z; acc[2][3] += A2.C * bv.w;           \
                acc[3][0] += A3.C * bv.x; acc[3][1] += A3.C * bv.y;           \
                acc[3][2] += A3.C * bv.z; acc[3][3] += A3.C * bv.w;           \
            }
            QCM_STEP(0, x)
            QCM_STEP(1, y)
            QCM_STEP(2, z)
            QCM_STEP(3, w)
#undef QCM_STEP
        }
        __syncthreads();
    }

    // ---- H = relu(acc + b1) into smem (overlays GEMM tiles) ----
    #pragma unroll
    for (int i = 0; i < 4; ++i) {
        int r = ty * 4 + i;
        #pragma unroll
        for (int j = 0; j < 4; ++j) {
            int n = tx * 4 + j;
            sm.Hs[r * 65 + n] = fmaxf(acc[i][j] + b1s[n], 0.0f);
        }
    }
    __syncthreads();

    // ---- v = tanh(H @ W2 + b2); 4 threads per row, 4 outputs each ----
    {
        int row = t >> 2;
        int seg = t & 3;
        float4 bb = *(const float4*)&b2s[seg * 4];
        float s0 = bb.x, s1 = bb.y, s2 = bb.z, s3 = bb.w;
        #pragma unroll 16
        for (int kk = 0; kk < 64; ++kk) {
            float  h = sm.Hs[row * 65 + kk];
            float4 w = *(const float4*)&W2s[kk * 16 + seg * 4];
            s0 += h * w.x; s1 += h * w.y; s2 += h * w.z; s3 += h * w.w;
        }
        s0 = tanhf(s0); s1 = tanhf(s1); s2 = tanhf(s2); s3 = tanhf(s3);
        float sq = s0 * s0 + s1 * s1 + s2 * s2 + s3 * s3;
        sq += __shfl_xor_sync(0xffffffffu, sq, 1);
        sq += __shfl_xor_sync(0xffffffffu, sq, 2);
        *(float4*)&Vs[row * 16 + seg * 4] = make_float4(s0, s1, s2, s3);
        if (seg == 0) ssq[row] = sq;
    }
    __syncthreads();

    // ---- fid = (va.vb)^2 / (|va|^2 |vb|^2), clipped ----
    if (t < 128) {
        int p   = t >> 2;
        int seg = t & 3;
        float4 a = *(const float4*)&Vs[p * 16 + seg * 4];
        float4 b = *(const float4*)&Vs[(p + 32) * 16 + seg * 4];
        float d = a.x * b.x + a.y * b.y + a.z * b.z + a.w * b.w;
        d += __shfl_xor_sync(0xffffffffu, d, 1);
        d += __shfl_xor_sync(0xffffffffu, d, 2);
        if (seg == 0) {
            float fid = (d * d) / (ssq[p] * ssq[p + 32]);
            out[p0 + p] = fminf(fmaxf(fid, 0.0f), 1.0f);
        }
    }
}

extern "C" void kernel_launch(void* const* d_in, const int* in_sizes, int n_in,
                              void* d_out, int out_size)
{
    const float* img_a = (const float*)d_in[0];
    const float* img_b = (const float*)d_in[1];
    const float* W1    = (const float*)d_in[2];
    const float* b1    = (const float*)d_in[3];
    const float* W2    = (const float*)d_in[4];
    const float* b2    = (const float*)d_in[5];
    // d_in[6] = theta: unused — the circuit is unitary, fidelity is invariant.
    float* out = (float*)d_out;

    int pairs  = out_size;          // 65536
    int blocks = pairs / 32;        // 32 pairs per block
    qcm_fused<<<blocks, 256>>>(img_a, img_b, W1, b1, W2, b2, out);
}

// round 5
// speedup vs baseline: 2.1384x; 2.1120x over previous
#include <cuda_runtime.h>
#include <cuda_bf16.h>
#include <cstdint>

// fid[p] = clip( (va.vb)^2 / (|va|^2 |vb|^2), 0, 1 )
// va = tanh( relu(xa @ W1 + b1) @ W2 + b2 )   (quantum circuit is unitary -> cancels)
//
// GEMM1 (131072 x 784 x 64) via mma.sync m16n8k16 bf16, split hi/lo (3 MMAs) for fp32-class accuracy.
// NOTE: harness PTX targets sm_103 (no 'a') -> tcgen05/TMA unavailable; mma.sync is the tensor path.

#define KDIM   784
#define KC     16
#define NCHUNK 49        // 784 / 16 exactly
#define ASTR   24        // bf16 elems per smem row (48 B) -> conflict-free 8x16B pattern
#define HSTR   66

#define MMA(d, a, b) asm volatile( \
    "mma.sync.aligned.m16n8k16.row.col.f32.bf16.bf16.f32 " \
    "{%0,%1,%2,%3}, {%4,%5,%6,%7}, {%8,%9}, {%0,%1,%2,%3};" \
    : "+f"(d[0]), "+f"(d[1]), "+f"(d[2]), "+f"(d[3]) \
    : "r"(a[0]), "r"(a[1]), "r"(a[2]), "r"(a[3]), "r"(b[0]), "r"(b[1]))

__device__ __forceinline__ uint32_t bf2u(__nv_bfloat162 v) { return *(uint32_t*)&v; }

// convert float4 -> 4x(hi,lo) bf16, store 8B hi + 8B lo
__device__ __forceinline__ void cvst4(float4 v, uint16_t* hi, uint16_t* lo) {
    __nv_bfloat162 h0 = __float22bfloat162_rn(make_float2(v.x, v.y));
    __nv_bfloat162 h1 = __float22bfloat162_rn(make_float2(v.z, v.w));
    __nv_bfloat162 l0 = __float22bfloat162_rn(make_float2(
        v.x - __bfloat162float(h0.x), v.y - __bfloat162float(h0.y)));
    __nv_bfloat162 l1 = __float22bfloat162_rn(make_float2(
        v.z - __bfloat162float(h1.x), v.w - __bfloat162float(h1.y)));
    *(uint2*)hi = make_uint2(bf2u(h0), bf2u(h1));
    *(uint2*)lo = make_uint2(bf2u(l0), bf2u(l1));
}

__global__ __launch_bounds__(256)
void qcm_mma(const float* __restrict__ img_a,
             const float* __restrict__ img_b,
             const float* __restrict__ W1,
             const float* __restrict__ b1,
             const float* __restrict__ W2,
             const float* __restrict__ b2,
             float* __restrict__ out)
{
    __shared__ union {
        struct {
            uint16_t Ahi[2][128 * ASTR];   // 2 x 6144 B
            uint16_t Alo[2][128 * ASTR];
            uint16_t Bhi[2][64 * ASTR];    // 2 x 3072 B
            uint16_t Blo[2][64 * ASTR];
        } m;                               // 30720 B
        struct {
            float H[128 * HSTR];           // 33792 B
            float Vs[128 * 16];
            float ssq[128];
        } e;                               // 42496 B
    } sm;
    __shared__ float W2s[64 * 16];
    __shared__ float b1s[64];
    __shared__ float b2s[16];

    const int t    = threadIdx.x;
    const int lane = t & 31;
    const int wid  = t >> 5;
    const int wr   = wid >> 1;        // 0..3 : 32-row group
    const int wc   = wid & 1;         // 0..1 : 32-col group
    const int g    = lane >> 2;       // group id 0..7
    const int tig  = lane & 3;        // thread in group
    const int p0   = blockIdx.x * 64; // 64 pairs per block

    // params
    if (t < 64) b1s[t] = b1[t];
    if (t < 16) b2s[t] = b2[t];
    #pragma unroll
    for (int i = 0; i < 4; ++i) W2s[t + i * 256] = W2[t + i * 256];

    // staging indices
    const int arow = t >> 1;                 // 0..127
    const int ak   = (t & 1) * 8;            // k offset within chunk
    const float* abase = (arow < 64 ? img_a + (size_t)(p0 + arow) * KDIM
                                    : img_b + (size_t)(p0 + arow - 64) * KDIM);
    const int bn   = t & 63;
    const int bk4  = (t >> 6) * 4;

    float acc[2][4][4];
    #pragma unroll
    for (int mt = 0; mt < 2; ++mt)
        #pragma unroll
        for (int nt = 0; nt < 4; ++nt)
            #pragma unroll
            for (int j = 0; j < 4; ++j) acc[mt][nt][j] = 0.f;

    // prologue: stage chunk 0
    {
        float4 v0 = *(const float4*)(abase + 0);
        float4 v1 = *(const float4*)(abase + 4 + (ak ? 4 : -4) + (ak ? 0 : 0));
        // (compute explicitly below instead)
        v0 = *(const float4*)(abase + ak);
        v1 = *(const float4*)(abase + ak + 4);
        cvst4(v0, &sm.m.Ahi[0][arow * ASTR + ak],     &sm.m.Alo[0][arow * ASTR + ak]);
        cvst4(v1, &sm.m.Ahi[0][arow * ASTR + ak + 4], &sm.m.Alo[0][arow * ASTR + ak + 4]);
        float4 w;
        w.x = W1[(size_t)(bk4 + 0) * 64 + bn];
        w.y = W1[(size_t)(bk4 + 1) * 64 + bn];
        w.z = W1[(size_t)(bk4 + 2) * 64 + bn];
        w.w = W1[(size_t)(bk4 + 3) * 64 + bn];
        cvst4(w, &sm.m.Bhi[0][bn * ASTR + bk4], &sm.m.Blo[0][bn * ASTR + bk4]);
    }
    __syncthreads();

    for (int c = 0; c < NCHUNK; ++c) {
        const int st = c & 1;

        // prefetch next chunk into registers (hide gmem latency under MMAs)
        float4 va0, va1, wb;
        if (c < NCHUNK - 1) {
            const int k0 = (c + 1) * KC;
            va0 = *(const float4*)(abase + k0 + ak);
            va1 = *(const float4*)(abase + k0 + ak + 4);
            wb.x = W1[(size_t)(k0 + bk4 + 0) * 64 + bn];
            wb.y = W1[(size_t)(k0 + bk4 + 1) * 64 + bn];
            wb.z = W1[(size_t)(k0 + bk4 + 2) * 64 + bn];
            wb.w = W1[(size_t)(k0 + bk4 + 3) * 64 + bn];
        }

        // fragments
        const uint16_t* Ah = sm.m.Ahi[st];
        const uint16_t* Al = sm.m.Alo[st];
        const uint16_t* Bh = sm.m.Bhi[st];
        const uint16_t* Bl = sm.m.Blo[st];

        uint32_t bh[4][2], bl[4][2];
        #pragma unroll
        for (int nt = 0; nt < 4; ++nt) {
            int bb = (wc * 32 + nt * 8 + g) * ASTR + 2 * tig;
            bh[nt][0] = *(const uint32_t*)&Bh[bb];
            bh[nt][1] = *(const uint32_t*)&Bh[bb + 8];
            bl[nt][0] = *(const uint32_t*)&Bl[bb];
            bl[nt][1] = *(const uint32_t*)&Bl[bb + 8];
        }

        #pragma unroll
        for (int mt = 0; mt < 2; ++mt) {
            int r0 = (wr * 32 + mt * 16 + g) * ASTR + 2 * tig;
            uint32_t ah[4], al[4];
            ah[0] = *(const uint32_t*)&Ah[r0];
            ah[1] = *(const uint32_t*)&Ah[r0 + 8 * ASTR];
            ah[2] = *(const uint32_t*)&Ah[r0 + 8];
            ah[3] = *(const uint32_t*)&Ah[r0 + 8 * ASTR + 8];
            al[0] = *(const uint32_t*)&Al[r0];
            al[1] = *(const uint32_t*)&Al[r0 + 8 * ASTR];
            al[2] = *(const uint32_t*)&Al[r0 + 8];
            al[3] = *(const uint32_t*)&Al[r0 + 8 * ASTR + 8];
            #pragma unroll
            for (int nt = 0; nt < 4; ++nt) {
                MMA(acc[mt][nt], ah, bh[nt]);
                MMA(acc[mt][nt], ah, bl[nt]);
                MMA(acc[mt][nt], al, bh[nt]);
            }
        }

        if (c < NCHUNK - 1) {
            const int sn = st ^ 1;
            cvst4(va0, &sm.m.Ahi[sn][arow * ASTR + ak],     &sm.m.Alo[sn][arow * ASTR + ak]);
            cvst4(va1, &sm.m.Ahi[sn][arow * ASTR + ak + 4], &sm.m.Alo[sn][arow * ASTR + ak + 4]);
            cvst4(wb,  &sm.m.Bhi[sn][bn * ASTR + bk4],      &sm.m.Blo[sn][bn * ASTR + bk4]);
        }
        __syncthreads();
    }

    // ---- epilogue: H = relu(acc + b1) into smem (fragment layout scatter) ----
    #pragma unroll
    for (int mt = 0; mt < 2; ++mt) {
        #pragma unroll
        for (int nt = 0; nt < 4; ++nt) {
            int row = wr * 32 + mt * 16 + g;
            int col = wc * 32 + nt * 8 + 2 * tig;
            float bx = b1s[col], by = b1s[col + 1];
            *(float2*)&sm.e.H[row * HSTR + col] =
                make_float2(fmaxf(acc[mt][nt][0] + bx, 0.f), fmaxf(acc[mt][nt][1] + by, 0.f));
            *(float2*)&sm.e.H[(row + 8) * HSTR + col] =
                make_float2(fmaxf(acc[mt][nt][2] + bx, 0.f), fmaxf(acc[mt][nt][3] + by, 0.f));
        }
    }
    __syncthreads();

    // ---- v = tanh(H @ W2 + b2): 2 threads per row, 8 outs each ----
    {
        int row  = t >> 1;
        int half = t & 1;
        float s[8];
        float4 bb0 = *(const float4*)&b2s[half * 8];
        float4 bb1 = *(const float4*)&b2s[half * 8 + 4];
        s[0]=bb0.x; s[1]=bb0.y; s[2]=bb0.z; s[3]=bb0.w;
        s[4]=bb1.x; s[5]=bb1.y; s[6]=bb1.z; s[7]=bb1.w;
        #pragma unroll 8
        for (int kk = 0; kk < 64; ++kk) {
            float h = sm.e.H[row * HSTR + kk];
            float4 w0 = *(const float4*)&W2s[kk * 16 + half * 8];
            float4 w1 = *(const float4*)&W2s[kk * 16 + half * 8 + 4];
            s[0]+=h*w0.x; s[1]+=h*w0.y; s[2]+=h*w0.z; s[3]+=h*w0.w;
            s[4]+=h*w1.x; s[5]+=h*w1.y; s[6]+=h*w1.z; s[7]+=h*w1.w;
        }
        float sq = 0.f;
        #pragma unroll
        for (int j = 0; j < 8; ++j) { s[j] = tanhf(s[j]); sq += s[j] * s[j]; }
        sq += __shfl_xor_sync(0xffffffffu, sq, 1);
        // Vs written AFTER all H reads? H and Vs are disjoint regions -> safe.
        *(float4*)&sm.e.Vs[row * 16 + half * 8]     = make_float4(s[0], s[1], s[2], s[3]);
        *(float4*)&sm.e.Vs[row * 16 + half * 8 + 4] = make_float4(s[4], s[5], s[6], s[7]);
        if (half == 0) sm.e.ssq[row] = sq;
    }
    __syncthreads();

    // ---- fid = (va.vb)^2 / (|va|^2 |vb|^2), clipped ----
    if (t < 64) {
        float d = 0.f;
        #pragma unroll
        for (int j4 = 0; j4 < 4; ++j4) {
            float4 a = *(const float4*)&sm.e.Vs[t * 16 + j4 * 4];
            float4 b = *(const float4*)&sm.e.Vs[(t + 64) * 16 + j4 * 4];
            d += a.x * b.x + a.y * b.y + a.z * b.z + a.w * b.w;
        }
        float fid = (d * d) / (sm.e.ssq[t] * sm.e.ssq[t + 64]);
        out[p0 + t] = fminf(fmaxf(fid, 0.f), 1.f);
    }
}

extern "C" void kernel_launch(void* const* d_in, const int* in_sizes, int n_in,
                              void* d_out, int out_size)
{
    const float* img_a = (const float*)d_in[0];
    const float* img_b = (const float*)d_in[1];
    const float* W1    = (const float*)d_in[2];
    const float* b1    = (const float*)d_in[3];
    const float* W2    = (const float*)d_in[4];
    const float* b2    = (const float*)d_in[5];
    // d_in[6] = theta: unused — the circuit is unitary, fidelity is invariant.
    float* out = (float*)d_out;

    int blocks = out_size / 64;   // 1024
    qcm_mma<<<blocks, 256>>>(img_a, img_b, W1, b1, W2, b2, out);
}